// round 10
// baseline (speedup 1.0000x reference)
#include <cuda_runtime.h>
#include <cuda_fp16.h>
#include <cstdint>

// FlashAttention B=4,H=12,S=4096,D=64, TILE=128, fp32 in/out.
// mma.sync m16n8k16 fp16 (plain sm_103 target — tcgen05 unavailable).
// Reference recurrence kept exactly: p = exp(s + mx - 2*nm),
// O = O*exp(m-nm) + P@V, ssum = ssum*exp(m-nm) + rowsum(P).
// Base-2 softmax domain (Q pre-scaled by 0.125*log2 e).
//
// R10: split-KV warp pairs. 256-thr CTA, 8 warps; warps g and g+4 share
// q-rows 16g..16g+15 and split the 128 kv columns (64 each) -> per-warp
// register state halves, fitting 128 regs @ 2 CTAs/SM = 16 warps/SM
// (4 per SMSP) for latency hiding. Pair-local named barrier for the
// per-iter row-max exchange; partial O/rowsum merged at epilogue.

#define S_LEN 4096
#define NKT   32
#define BH_N  48

#define TILEB 16384          // 128 rows x 128 bytes
#define QOFF  0              // 64 rows x 128B = 8KB (reused: stats after qA)
#define KOFF  8192
#define VOFF  (8192 + 2*16384)
#define SMEM_MAIN (8192 + 4*16384)   // 73728

__device__ __align__(128) __half g_Qh[(size_t)BH_N * S_LEN * 64];
__device__ __align__(128) __half g_Kh[(size_t)BH_N * S_LEN * 64];
__device__ __align__(128) __half g_Vh[(size_t)BH_N * S_LEN * 64];

// ---------------- pre-kernel: fp32 -> fp16 (Q scaled by 0.125*log2e) --------
__global__ void __launch_bounds__(256) cvt_pre(const float4* __restrict__ Q,
                                               const float4* __restrict__ K,
                                               const float4* __restrict__ V)
{
    const int PER = (int)((size_t)BH_N * S_LEN * 64 / 4);
    int gid = blockIdx.x * 256 + threadIdx.x;
    int stride = gridDim.x * 256;
    for (int i = gid; i < 3 * PER; i += stride) {
        int t = i / PER, off = i - t * PER;
        const float4* src = (t == 0) ? Q : (t == 1) ? K : V;
        uint2* dst = (uint2*)((t == 0) ? g_Qh : (t == 1) ? g_Kh : g_Vh);
        float s = (t == 0) ? 0.125f * 1.44269504f : 1.0f;
        float4 v = src[off];
        __half2 h0 = __floats2half2_rn(v.x * s, v.y * s);
        __half2 h1 = __floats2half2_rn(v.z * s, v.w * s);
        uint2 w;
        w.x = *(uint32_t*)&h0;
        w.y = *(uint32_t*)&h1;
        dst[off] = w;
    }
}

// ---------------- helpers ----------------
__device__ __forceinline__ uint32_t smem_u32(const void* p){
    uint32_t a; asm("{ .reg .u64 t; cvta.to.shared.u64 t, %1; cvt.u32.u64 %0, t; }"
                    : "=r"(a) : "l"(p)); return a;
}
__device__ __forceinline__ void cpa16(uint32_t dst, const void* src){
    asm volatile("cp.async.cg.shared.global [%0], [%1], 16;" :: "r"(dst), "l"(src));
}
__device__ __forceinline__ void ldsm4(uint32_t& r0, uint32_t& r1, uint32_t& r2,
                                      uint32_t& r3, uint32_t a){
    asm volatile("ldmatrix.sync.aligned.m8n8.x4.shared.b16 {%0,%1,%2,%3}, [%4];"
                 : "=r"(r0), "=r"(r1), "=r"(r2), "=r"(r3) : "r"(a));
}
__device__ __forceinline__ void ldsm4t(uint32_t& r0, uint32_t& r1, uint32_t& r2,
                                       uint32_t& r3, uint32_t a){
    asm volatile("ldmatrix.sync.aligned.m8n8.x4.trans.shared.b16 {%0,%1,%2,%3}, [%4];"
                 : "=r"(r0), "=r"(r1), "=r"(r2), "=r"(r3) : "r"(a));
}
__device__ __forceinline__ void mma168(float* d, const uint32_t* a,
                                       uint32_t b0, uint32_t b1){
    asm volatile(
        "mma.sync.aligned.m16n8k16.row.col.f32.f16.f16.f32 "
        "{%0,%1,%2,%3}, {%4,%5,%6,%7}, {%8,%9}, {%0,%1,%2,%3};"
        : "+f"(d[0]), "+f"(d[1]), "+f"(d[2]), "+f"(d[3])
        : "r"(a[0]), "r"(a[1]), "r"(a[2]), "r"(a[3]), "r"(b0), "r"(b1));
}
__device__ __forceinline__ uint32_t exp2_h2(float lo, float hi, float adj){
    __half2 h = __floats2half2_rn(lo + adj, hi + adj);
    h = h2exp2(h);
    return *(uint32_t*)&h;
}

// stage one K tile + one V tile (fp16, 16KB each), 256 threads, XOR swizzle
__device__ __forceinline__ void stage_kv(uint32_t sb, int buf, int tid,
                                         const __half* gk, const __half* gv){
    const int row0 = tid >> 3, c = tid & 7;
    const uint32_t sw = (uint32_t)((c ^ (row0 & 7)) << 4);
    uint32_t dk = sb + KOFF + buf * TILEB + row0 * 128 + sw;
    uint32_t dv = sb + VOFF + buf * TILEB + row0 * 128 + sw;
    const __half* sk = gk + row0 * 64 + c * 8;
    const __half* sv = gv + row0 * 64 + c * 8;
    #pragma unroll
    for (int i = 0; i < 4; i++){
        cpa16(dk, sk); dk += 4096; sk += 2048;
        cpa16(dv, sv); dv += 4096; sv += 2048;
    }
    asm volatile("cp.async.commit_group;" ::: "memory");
}

// ---------- main kernel: 256 thr, warp pairs split kv, 2 CTAs/SM ------------
__global__ void __launch_bounds__(256, 2)
fa_mma(float* __restrict__ O)
{
    extern __shared__ char smraw[];
    const uint32_t sb = smem_u32(smraw);
    float* sStat = (float*)smraw;              // QOFF region reused after qA
    const int tid  = threadIdx.x;
    const int lane = tid & 31;
    const int w    = tid >> 5;
    const int g    = w & 3;                    // row group: q rows 16g..16g+15
    const int h    = w >> 2;                   // kv half: cols 64h..64h+63
    const int bh   = blockIdx.x >> 6;
    const int qt   = blockIdx.x & 63;          // 64-row q tiles

    const __half* gq = g_Qh + ((size_t)bh * S_LEN + (size_t)qt * 64) * 64;
    const __half* gk = g_Kh + (size_t)bh * S_LEN * 64;
    const __half* gv = g_Vh + (size_t)bh * S_LEN * 64;

    const uint32_t xk = (uint32_t)(lane & 7) << 4;

    // stage Q (64 rows, 8KB) + KV tile 0
    {
        const int row0 = tid >> 3, c = tid & 7;
        const uint32_t sw = (uint32_t)((c ^ (row0 & 7)) << 4);
        uint32_t dq = sb + QOFF + row0 * 128 + sw;
        const __half* sq = gq + row0 * 64 + c * 8;
        #pragma unroll
        for (int i = 0; i < 2; i++){ cpa16(dq, sq); dq += 4096; sq += 2048; }
    }
    stage_kv(sb, 0, tid, gk, gv);
    asm volatile("cp.async.wait_group 0;" ::: "memory");
    __syncthreads();

    // Q A-fragments (persist; same rows for both warps of a pair)
    uint32_t qA[4][4];
    {
        int qrow = 16 * g + (lane & 15);
        int qc   = lane >> 4;
        uint32_t qb = sb + QOFF + qrow * 128;
        #pragma unroll
        for (int k = 0; k < 4; k++)
            ldsm4(qA[k][0], qA[k][1], qA[k][2], qA[k][3],
                  qb + ((uint32_t)((2 * k + qc) << 4) ^ xk));
    }
    __syncthreads();    // Q smem now dead -> sStat may be written

    const int rbK = (lane & 7) + ((lane >> 4) << 3);
    const int cbK = (lane >> 3) & 1;
    const int rbV = (lane & 7) + (((lane >> 3) & 1) << 3);
    const int cbV = lane >> 4;
    uint32_t ckK[4], ckV[4];
    #pragma unroll
    for (int k = 0; k < 4; k++){
        ckK[k] = ((uint32_t)((2 * k + cbK) << 4)) ^ xk;
        ckV[k] = ((uint32_t)((2 * k + cbV) << 4)) ^ xk;
    }
    const uint32_t bone = (lane < 4) ? 0x3C003C00u : 0u;
    const int rowA = 16 * g + (lane >> 2);         // stat row (mx1)
    const int sOwn = h * 64, sOth = 64 - h * 64;   // stat bases

    float o[9][4];                                 // 8 D-tiles + rowsum tile
    #pragma unroll
    for (int t = 0; t < 9; t++)
        #pragma unroll
        for (int c = 0; c < 4; c++) o[t][c] = 0.0f;
    float m1 = -INFINITY, m2 = -INFINITY;

    for (int kt = 0; kt < NKT; kt++){
        const int buf = kt & 1;
        if (kt + 1 < NKT)
            stage_kv(sb, buf ^ 1, tid, gk + (size_t)(kt + 1) * 8192,
                                       gv + (size_t)(kt + 1) * 8192);

        // ---- MMA1: S = Q @ K^T over this warp's 64 kv cols ----
        float acc[8][4];
        #pragma unroll
        for (int t = 0; t < 8; t++)
            #pragma unroll
            for (int c = 0; c < 4; c++) acc[t][c] = 0.0f;

        float mx1 = -INFINITY, mx2 = -INFINITY;
        {
            uint32_t krow = sb + KOFF + buf * TILEB + h * 8192 + rbK * 128;
            #pragma unroll
            for (int j4 = 0; j4 < 4; j4++){
                #pragma unroll
                for (int k = 0; k < 4; k++){
                    uint32_t b0, b1, b2, b3;
                    ldsm4(b0, b1, b2, b3, krow + ckK[k]);
                    mma168(acc[2 * j4],     qA[k], b0, b1);
                    mma168(acc[2 * j4 + 1], qA[k], b2, b3);
                }
                krow += 2048;
                mx1 = fmaxf(mx1, fmaxf(fmaxf(acc[2*j4][0], acc[2*j4][1]),
                                       fmaxf(acc[2*j4+1][0], acc[2*j4+1][1])));
                mx2 = fmaxf(mx2, fmaxf(fmaxf(acc[2*j4][2], acc[2*j4][3]),
                                       fmaxf(acc[2*j4+1][2], acc[2*j4+1][3])));
            }
        }

        mx1 = fmaxf(mx1, __shfl_xor_sync(0xffffffffu, mx1, 1));
        mx1 = fmaxf(mx1, __shfl_xor_sync(0xffffffffu, mx1, 2));
        mx2 = fmaxf(mx2, __shfl_xor_sync(0xffffffffu, mx2, 1));
        mx2 = fmaxf(mx2, __shfl_xor_sync(0xffffffffu, mx2, 2));

        // ---- pair exchange: full-row max over both kv halves ----
        if ((lane & 3) == 0){
            sStat[sOwn + rowA]     = mx1;
            sStat[sOwn + rowA + 8] = mx2;
        }
        asm volatile("bar.sync %0, 64;" :: "r"(g + 1) : "memory");
        mx1 = fmaxf(mx1, sStat[sOth + rowA]);
        mx2 = fmaxf(mx2, sStat[sOth + rowA + 8]);

        const float nm1 = fmaxf(m1, mx1), nm2 = fmaxf(m2, mx2);
        const float adj1 = mx1 - 2.0f * nm1, adj2 = mx2 - 2.0f * nm2;
        const float osc1 = exp2f(m1 - nm1), osc2 = exp2f(m2 - nm2);
        const bool changed = (nm1 != m1) | (nm2 != m2);
        m1 = nm1; m2 = nm2;

        if (__any_sync(0xffffffffu, changed)){
            #pragma unroll
            for (int t = 0; t < 9; t++){
                o[t][0] *= osc1; o[t][1] *= osc1;
                o[t][2] *= osc2; o[t][3] *= osc2;
            }
        }

        // ---- bulk P conversion (acc dies; pl/ph take its space) ----
        uint32_t pl[8], ph[8];
        #pragma unroll
        for (int t = 0; t < 8; t++){
            pl[t] = exp2_h2(acc[t][0], acc[t][1], adj1);
            ph[t] = exp2_h2(acc[t][2], acc[t][3], adj2);
        }

        // ---- MMA2: partial O += P_half @ V_half ----
        {
            uint32_t vrow = sb + VOFF + buf * TILEB + h * 8192 + rbV * 128;
            #pragma unroll
            for (int kk = 0; kk < 4; kk++){
                uint32_t aA[4] = { pl[2*kk], ph[2*kk], pl[2*kk+1], ph[2*kk+1] };
                #pragma unroll
                for (int j4 = 0; j4 < 4; j4++){
                    uint32_t b0, b1, b2, b3;
                    ldsm4t(b0, b1, b2, b3, vrow + ckV[j4]);
                    mma168(o[2 * j4],     aA, b0, b1);
                    mma168(o[2 * j4 + 1], aA, b2, b3);
                }
                mma168(o[8], aA, bone, bone);
                vrow += 2048;
            }
        }

        asm volatile("cp.async.wait_group 0;" ::: "memory");
        __syncthreads();
    }

    // ---- epilogue: merge warp-pair partials, divide, store ----
    // half 1 writes its 36 floats into dead K-buffer smem; half 0 adds.
    {
        float* sX = (float*)(smraw + KOFF);
        if (h == 1){
            float* p = sX + (g * 32 + lane) * 36;
            #pragma unroll
            for (int t = 0; t < 9; t++){
                p[4*t+0] = o[t][0]; p[4*t+1] = o[t][1];
                p[4*t+2] = o[t][2]; p[4*t+3] = o[t][3];
            }
        }
        __syncthreads();
        if (h == 0){
            const float* p = sX + (g * 32 + lane) * 36;
            #pragma unroll
            for (int t = 0; t < 9; t++){
                o[t][0] += p[4*t+0]; o[t][1] += p[4*t+1];
                o[t][2] += p[4*t+2]; o[t][3] += p[4*t+3];
            }
            float sum1 = __shfl_sync(0xffffffffu, o[8][0], lane & ~3);
            float sum2 = __shfl_sync(0xffffffffu, o[8][2], lane & ~3);
            const float inv1 = 1.0f / sum1, inv2 = 1.0f / sum2;
            const int r1 = 16 * g + (lane >> 2);
            float* Ob = O + ((size_t)bh * S_LEN + (size_t)qt * 64) * 64;
            #pragma unroll
            for (int t = 0; t < 8; t++){
                int col = 8 * t + (lane & 3) * 2;
                *(float2*)(Ob + (size_t)r1 * 64 + col) =
                    make_float2(o[t][0] * inv1, o[t][1] * inv1);
                *(float2*)(Ob + (size_t)(r1 + 8) * 64 + col) =
                    make_float2(o[t][2] * inv2, o[t][3] * inv2);
            }
        }
    }
}

extern "C" void kernel_launch(void* const* d_in, const int* in_sizes, int n_in,
                              void* d_out, int out_size)
{
    const float4* Q = (const float4*)d_in[0];
    const float4* K = (const float4*)d_in[1];
    const float4* V = (const float4*)d_in[2];
    float* Ot = (float*)d_out;

    cudaFuncSetAttribute(fa_mma, cudaFuncAttributeMaxDynamicSharedMemorySize, SMEM_MAIN);
    cvt_pre<<<9216, 256>>>(Q, K, V);
    fa_mma<<<BH_N * 64, 256, SMEM_MAIN>>>(Ot);
}

// round 11
// speedup vs baseline: 1.1291x; 1.1291x over previous
#include <cuda_runtime.h>
#include <cuda_fp16.h>
#include <cstdint>

// FlashAttention B=4,H=12,S=4096,D=64, TILE=128, fp32 in/out.
// mma.sync m16n8k16 fp16 (plain sm_103 target — tcgen05 unavailable).
// Reference recurrence kept exactly: p = exp(s + mx - 2*nm),
// O = O*exp(m-nm) + P@V, ssum = ssum*exp(m-nm) + rowsum(P).
// Base-2 softmax domain (Q pre-scaled by 0.125*log2 e).
//
// R11: R8 configuration (best measured: 3 CTAs/SM, 128 thr, 64 q-rows,
// fused partial row-max, bulk P conversion) + zero-C first MMA per strip
// (acc zero-init MOVs eliminated via C=RZ on the k=0 HMMA).

#define S_LEN 4096
#define NKT   32
#define BH_N  48

#define TILEB 16384          // 128 rows x 128 bytes
#define QOFF  0              // 64 rows x 128B = 8KB
#define KOFF  8192
#define VOFF  (8192 + 2*16384)
#define SMEM_MAIN (8192 + 4*16384)   // 73728

__device__ __align__(128) __half g_Qh[(size_t)BH_N * S_LEN * 64];
__device__ __align__(128) __half g_Kh[(size_t)BH_N * S_LEN * 64];
__device__ __align__(128) __half g_Vh[(size_t)BH_N * S_LEN * 64];

// ---------------- pre-kernel: fp32 -> fp16 (Q scaled by 0.125*log2e) --------
__global__ void __launch_bounds__(256) cvt_pre(const float4* __restrict__ Q,
                                               const float4* __restrict__ K,
                                               const float4* __restrict__ V)
{
    const int PER = (int)((size_t)BH_N * S_LEN * 64 / 4);
    int gid = blockIdx.x * 256 + threadIdx.x;
    int stride = gridDim.x * 256;
    for (int i = gid; i < 3 * PER; i += stride) {
        int t = i / PER, off = i - t * PER;
        const float4* src = (t == 0) ? Q : (t == 1) ? K : V;
        uint2* dst = (uint2*)((t == 0) ? g_Qh : (t == 1) ? g_Kh : g_Vh);
        float s = (t == 0) ? 0.125f * 1.44269504f : 1.0f;
        float4 v = src[off];
        __half2 h0 = __floats2half2_rn(v.x * s, v.y * s);
        __half2 h1 = __floats2half2_rn(v.z * s, v.w * s);
        uint2 w;
        w.x = *(uint32_t*)&h0;
        w.y = *(uint32_t*)&h1;
        dst[off] = w;
    }
}

// ---------------- helpers ----------------
__device__ __forceinline__ uint32_t smem_u32(const void* p){
    uint32_t a; asm("{ .reg .u64 t; cvta.to.shared.u64 t, %1; cvt.u32.u64 %0, t; }"
                    : "=r"(a) : "l"(p)); return a;
}
__device__ __forceinline__ void cpa16(uint32_t dst, const void* src){
    asm volatile("cp.async.cg.shared.global [%0], [%1], 16;" :: "r"(dst), "l"(src));
}
__device__ __forceinline__ void ldsm4(uint32_t& r0, uint32_t& r1, uint32_t& r2,
                                      uint32_t& r3, uint32_t a){
    asm volatile("ldmatrix.sync.aligned.m8n8.x4.shared.b16 {%0,%1,%2,%3}, [%4];"
                 : "=r"(r0), "=r"(r1), "=r"(r2), "=r"(r3) : "r"(a));
}
__device__ __forceinline__ void ldsm4t(uint32_t& r0, uint32_t& r1, uint32_t& r2,
                                       uint32_t& r3, uint32_t a){
    asm volatile("ldmatrix.sync.aligned.m8n8.x4.trans.shared.b16 {%0,%1,%2,%3}, [%4];"
                 : "=r"(r0), "=r"(r1), "=r"(r2), "=r"(r3) : "r"(a));
}
__device__ __forceinline__ void mma168(float* d, const uint32_t* a,
                                       uint32_t b0, uint32_t b1){
    asm volatile(
        "mma.sync.aligned.m16n8k16.row.col.f32.f16.f16.f32 "
        "{%0,%1,%2,%3}, {%4,%5,%6,%7}, {%8,%9}, {%0,%1,%2,%3};"
        : "+f"(d[0]), "+f"(d[1]), "+f"(d[2]), "+f"(d[3])
        : "r"(a[0]), "r"(a[1]), "r"(a[2]), "r"(a[3]), "r"(b0), "r"(b1));
}
// first k-step: C = 0 (RZ) — no accumulator zero-init needed
__device__ __forceinline__ void mma168_z(float* d, const uint32_t* a,
                                         uint32_t b0, uint32_t b1){
    asm volatile(
        "mma.sync.aligned.m16n8k16.row.col.f32.f16.f16.f32 "
        "{%0,%1,%2,%3}, {%4,%5,%6,%7}, {%8,%9}, {%10,%10,%10,%10};"
        : "=f"(d[0]), "=f"(d[1]), "=f"(d[2]), "=f"(d[3])
        : "r"(a[0]), "r"(a[1]), "r"(a[2]), "r"(a[3]), "r"(b0), "r"(b1),
          "f"(0.0f));
}
__device__ __forceinline__ uint32_t exp2_h2(float lo, float hi, float adj){
    __half2 h = __floats2half2_rn(lo + adj, hi + adj);
    h = h2exp2(h);
    return *(uint32_t*)&h;
}

// stage one K tile + one V tile (fp16, 16KB each), 128 threads, XOR swizzle
__device__ __forceinline__ void stage_kv(uint32_t sb, int buf, int tid,
                                         const __half* gk, const __half* gv){
    const int row0 = tid >> 3, c = tid & 7;
    const uint32_t sw = (uint32_t)((c ^ (row0 & 7)) << 4);
    uint32_t dk = sb + KOFF + buf * TILEB + row0 * 128 + sw;
    uint32_t dv = sb + VOFF + buf * TILEB + row0 * 128 + sw;
    const __half* sk = gk + row0 * 64 + c * 8;
    const __half* sv = gv + row0 * 64 + c * 8;
    #pragma unroll
    for (int i = 0; i < 8; i++){
        cpa16(dk, sk); dk += 2048; sk += 1024;
        cpa16(dv, sv); dv += 2048; sv += 1024;
    }
    asm volatile("cp.async.commit_group;" ::: "memory");
}

// ---------------- main kernel: 128 threads, 64 q-rows, 3 CTAs/SM ------------
__global__ void __launch_bounds__(128, 3)
fa_mma(float* __restrict__ O)
{
    extern __shared__ char smraw[];
    const uint32_t sb = smem_u32(smraw);
    const int tid  = threadIdx.x;
    const int lane = tid & 31;
    const int w    = tid >> 5;
    const int bh   = blockIdx.x >> 6;
    const int qt   = blockIdx.x & 63;

    const __half* gq = g_Qh + ((size_t)bh * S_LEN + (size_t)qt * 64) * 64;
    const __half* gk = g_Kh + (size_t)bh * S_LEN * 64;
    const __half* gv = g_Vh + (size_t)bh * S_LEN * 64;

    const uint32_t xk = (uint32_t)(lane & 7) << 4;

    // stage Q (8KB) + KV tile 0
    {
        const int row0 = tid >> 3, c = tid & 7;
        const uint32_t sw = (uint32_t)((c ^ (row0 & 7)) << 4);
        uint32_t dq = sb + QOFF + row0 * 128 + sw;
        const __half* sq = gq + row0 * 64 + c * 8;
        #pragma unroll
        for (int i = 0; i < 4; i++){ cpa16(dq, sq); dq += 2048; sq += 1024; }
    }
    stage_kv(sb, 0, tid, gk, gv);
    asm volatile("cp.async.wait_group 0;" ::: "memory");
    __syncthreads();

    // Q A-fragments (persist)
    uint32_t qA[4][4];
    {
        int qrow = 16 * w + (lane & 15);
        int qc   = lane >> 4;
        uint32_t qb = sb + QOFF + qrow * 128;
        #pragma unroll
        for (int k = 0; k < 4; k++)
            ldsm4(qA[k][0], qA[k][1], qA[k][2], qA[k][3],
                  qb + ((uint32_t)((2 * k + qc) << 4) ^ xk));
    }

    const int rbK = (lane & 7) + ((lane >> 4) << 3);
    const int cbK = (lane >> 3) & 1;
    const int rbV = (lane & 7) + (((lane >> 3) & 1) << 3);
    const int cbV = lane >> 4;
    uint32_t ckK[4], ckV[4];
    #pragma unroll
    for (int k = 0; k < 4; k++){
        ckK[k] = ((uint32_t)((2 * k + cbK) << 4)) ^ xk;
        ckV[k] = ((uint32_t)((2 * k + cbV) << 4)) ^ xk;
    }
    const uint32_t bone = (lane < 4) ? 0x3C003C00u : 0u;

    float o[9][4];
    #pragma unroll
    for (int t = 0; t < 9; t++)
        #pragma unroll
        for (int c = 0; c < 4; c++) o[t][c] = 0.0f;
    float m1 = -INFINITY, m2 = -INFINITY;

    for (int kt = 0; kt < NKT; kt++){
        const int buf = kt & 1;
        if (kt + 1 < NKT)
            stage_kv(sb, buf ^ 1, tid, gk + (size_t)(kt + 1) * 8192,
                                       gv + (size_t)(kt + 1) * 8192);

        // ---- MMA1 (k=0 writes acc with C=0) + fused partial row-max ----
        float acc[16][4];
        float mx1 = -INFINITY, mx2 = -INFINITY;
        {
            uint32_t krow = sb + KOFF + buf * TILEB + rbK * 128;
            #pragma unroll
            for (int j4 = 0; j4 < 8; j4++){
                {
                    uint32_t b0, b1, b2, b3;
                    ldsm4(b0, b1, b2, b3, krow + ckK[0]);
                    mma168_z(acc[2 * j4],     qA[0], b0, b1);
                    mma168_z(acc[2 * j4 + 1], qA[0], b2, b3);
                }
                #pragma unroll
                for (int k = 1; k < 4; k++){
                    uint32_t b0, b1, b2, b3;
                    ldsm4(b0, b1, b2, b3, krow + ckK[k]);
                    mma168(acc[2 * j4],     qA[k], b0, b1);
                    mma168(acc[2 * j4 + 1], qA[k], b2, b3);
                }
                krow += 2048;
                mx1 = fmaxf(mx1, fmaxf(fmaxf(acc[2*j4][0], acc[2*j4][1]),
                                       fmaxf(acc[2*j4+1][0], acc[2*j4+1][1])));
                mx2 = fmaxf(mx2, fmaxf(fmaxf(acc[2*j4][2], acc[2*j4][3]),
                                       fmaxf(acc[2*j4+1][2], acc[2*j4+1][3])));
            }
        }

        mx1 = fmaxf(mx1, __shfl_xor_sync(0xffffffffu, mx1, 1));
        mx1 = fmaxf(mx1, __shfl_xor_sync(0xffffffffu, mx1, 2));
        mx2 = fmaxf(mx2, __shfl_xor_sync(0xffffffffu, mx2, 1));
        mx2 = fmaxf(mx2, __shfl_xor_sync(0xffffffffu, mx2, 2));

        const float nm1 = fmaxf(m1, mx1), nm2 = fmaxf(m2, mx2);
        const float adj1 = mx1 - 2.0f * nm1, adj2 = mx2 - 2.0f * nm2;
        const float osc1 = exp2f(m1 - nm1), osc2 = exp2f(m2 - nm2);

        if (__any_sync(0xffffffffu, (nm1 != m1) | (nm2 != m2))){
            #pragma unroll
            for (int t = 0; t < 9; t++){
                o[t][0] *= osc1; o[t][1] *= osc1;
                o[t][2] *= osc2; o[t][3] *= osc2;
            }
        }
        m1 = nm1; m2 = nm2;

        // ---- bulk P conversion (acc dies; pl/ph take its space) ----
        uint32_t pl[16], ph[16];
        #pragma unroll
        for (int t = 0; t < 16; t++){
            pl[t] = exp2_h2(acc[t][0], acc[t][1], adj1);
            ph[t] = exp2_h2(acc[t][2], acc[t][3], adj2);
        }

        // ---- MMA2: O += P @ V ; rowsum via constant ones B-fragment ----
        {
            uint32_t vrow = sb + VOFF + buf * TILEB + rbV * 128;
            #pragma unroll
            for (int kk = 0; kk < 8; kk++){
                uint32_t aA[4] = { pl[2*kk], ph[2*kk], pl[2*kk+1], ph[2*kk+1] };
                #pragma unroll
                for (int j4 = 0; j4 < 4; j4++){
                    uint32_t b0, b1, b2, b3;
                    ldsm4t(b0, b1, b2, b3, vrow + ckV[j4]);
                    mma168(o[2 * j4],     aA, b0, b1);
                    mma168(o[2 * j4 + 1], aA, b2, b3);
                }
                mma168(o[8], aA, bone, bone);
                vrow += 2048;
            }
        }

        asm volatile("cp.async.wait_group 0;" ::: "memory");
        __syncthreads();
    }

    // ---- epilogue ----
    float sum1 = __shfl_sync(0xffffffffu, o[8][0], lane & ~3);
    float sum2 = __shfl_sync(0xffffffffu, o[8][2], lane & ~3);
    const float inv1 = 1.0f / sum1, inv2 = 1.0f / sum2;

    const int r1 = 16 * w + (lane >> 2);
    float* Ob = O + ((size_t)bh * S_LEN + (size_t)qt * 64) * 64;
    #pragma unroll
    for (int t = 0; t < 8; t++){
        int col = 8 * t + (lane & 3) * 2;
        *(float2*)(Ob + (size_t)r1 * 64 + col) =
            make_float2(o[t][0] * inv1, o[t][1] * inv1);
        *(float2*)(Ob + (size_t)(r1 + 8) * 64 + col) =
            make_float2(o[t][2] * inv2, o[t][3] * inv2);
    }
}

extern "C" void kernel_launch(void* const* d_in, const int* in_sizes, int n_in,
                              void* d_out, int out_size)
{
    const float4* Q = (const float4*)d_in[0];
    const float4* K = (const float4*)d_in[1];
    const float4* V = (const float4*)d_in[2];
    float* Ot = (float*)d_out;

    cudaFuncSetAttribute(fa_mma, cudaFuncAttributeMaxDynamicSharedMemorySize, SMEM_MAIN);
    cvt_pre<<<9216, 256>>>(Q, K, V);
    fa_mma<<<BH_N * 64, 128, SMEM_MAIN>>>(Ot);
}